// round 1
// baseline (speedup 1.0000x reference)
#include <cuda_runtime.h>
#include <math.h>

#define NB 16
#define NT 2048
#define NF 768
#define EPSV 1e-5f
#define TSPLIT 16
#define TCHUNK (NT / TSPLIT)   // 128

// Scratch (no device allocation allowed): partial sums per (t-chunk, b, f).
// Every slot is unconditionally overwritten each launch -> graph-replay safe.
__device__ int   g_actual[NB];
__device__ float g_S1[TSPLIT * NB * NF];
__device__ float g_S2[TSPLIT * NB * NF];

// ---------------------------------------------------------------------------
// Kernel 1: seq_lens[b] = sum(mask[b,:]); actual[b] = round(seq/max * 2048)
// Single CTA, 1024 threads: 64 threads per batch row.
// ---------------------------------------------------------------------------
__global__ void k_mask_actual(const int* __restrict__ mask) {
    __shared__ int sm[1024];
    const int tid = threadIdx.x;
    const int b   = tid >> 6;     // 0..15
    const int l   = tid & 63;     // 0..63

    int s = 0;
    const int* mp = mask + b * NT + l;
#pragma unroll
    for (int j = 0; j < NT / 64; j++) s += mp[j * 64];
    sm[tid] = s;
    __syncthreads();

#pragma unroll
    for (int off = 32; off >= 1; off >>= 1) {
        if (l < off) sm[tid] += sm[tid + off];
        __syncthreads();
    }

    if (tid == 0) {
        int smax = 0;
#pragma unroll
        for (int b2 = 0; b2 < NB; b2++) smax = max(smax, sm[b2 * 64]);
        const float fmx = (float)smax;
#pragma unroll
        for (int b2 = 0; b2 < NB; b2++) {
            // match jnp: fp32 divide, fp32 multiply by T, round-half-to-even
            float rel = (float)sm[b2 * 64] / fmx;
            g_actual[b2] = (int)rintf(rel * (float)NT);
        }
    }
}

// ---------------------------------------------------------------------------
// Kernel 2: partial sum / sum-of-squares over a 128-row T-chunk.
// grid = (NF/256, TSPLIT, NB), block = 256. Warp reads 1024B contiguous/iter.
// ---------------------------------------------------------------------------
__global__ void __launch_bounds__(256)
k_partial(const float* __restrict__ x) {
    const int f  = blockIdx.x * 256 + threadIdx.x;
    const int ts = blockIdx.y;
    const int b  = blockIdx.z;

    const int n  = g_actual[b];
    const int t0 = ts * TCHUNK;
    const int t1 = min(t0 + TCHUNK, n);

    float s1 = 0.0f, s2 = 0.0f;
    const float* p = x + ((size_t)b * NT + (size_t)t0) * NF + f;
#pragma unroll 8
    for (int t = t0; t < t1; t++, p += NF) {
        float v = *p;
        s1 += v;
        s2 = fmaf(v, v, s2);
    }
    const int idx = (ts * NB + b) * NF + f;
    g_S1[idx] = s1;
    g_S2[idx] = s2;
}

// ---------------------------------------------------------------------------
// Kernel 3: reduce TSPLIT partials, finalize mean/std, write [B, 1, 2F].
// ---------------------------------------------------------------------------
__global__ void __launch_bounds__(256)
k_final(float* __restrict__ out) {
    const int i = blockIdx.x * 256 + threadIdx.x;   // 0 .. NB*NF-1
    const int b = i / NF;
    const int f = i - b * NF;

    float s1 = 0.0f, s2 = 0.0f;
#pragma unroll
    for (int ts = 0; ts < TSPLIT; ts++) {
        const int idx = (ts * NB + b) * NF + f;
        s1 += g_S1[idx];
        s2 += g_S2[idx];
    }

    const float n    = (float)g_actual[b];
    const float mean = s1 / n;
    const float var  = (s2 - mean * s1) / (n - 1.0f);
    const float sd   = sqrtf(var) + EPSV;

    // NOTE: reference adds jax-threefry gauss noise in [1e-5, 9e-5] to mean.
    // Omitted: contributes ~8e-5 to normalized rel err (budget 1e-3).
    out[b * (2 * NF) + f]      = mean;
    out[b * (2 * NF) + NF + f] = sd;
}

// ---------------------------------------------------------------------------
extern "C" void kernel_launch(void* const* d_in, const int* in_sizes, int n_in,
                              void* d_out, int out_size) {
    const float* x    = (const float*)d_in[0];   // input_values [16,2048,768] f32
    const int*   mask = (const int*)d_in[1];     // attention_mask [16,2048] i32
    float*       out  = (float*)d_out;           // [16,1,1536] f32

    k_mask_actual<<<1, 1024>>>(mask);
    k_partial<<<dim3(NF / 256, TSPLIT, NB), 256>>>(x);
    k_final<<<(NB * NF) / 256, 256>>>(out);
}